// round 7
// baseline (speedup 1.0000x reference)
#include <cuda_runtime.h>
#include <cuda_bf16.h>
#include <cstdint>
#include <math.h>

// ---------------------------------------------------------------------------
// Problem dims
// ---------------------------------------------------------------------------
#define BQ   32
#define SDIM 2048
#define DQ   512
#define MTOT (BQ * SDIM)          // 65536

// ---------------------------------------------------------------------------
// Device scratch (static only)
// ---------------------------------------------------------------------------
__device__ __align__(256) __nv_bfloat16 g_keys_hi[MTOT * DQ];   // 64 MiB
__device__ __align__(256) __nv_bfloat16 g_keys_lo[MTOT * DQ];   // 64 MiB
__device__ __align__(256) __nv_bfloat16 g_w2_hi[DQ * DQ];
__device__ __align__(256) __nv_bfloat16 g_w2_lo[DQ * DQ];
__device__ float g_w1q[BQ * DQ];
__device__ float g_partial[2][MTOT];

// ---------------------------------------------------------------------------
// Portable tensor-core helpers: ldmatrix + mma.sync + cp.async
// ---------------------------------------------------------------------------
__device__ __forceinline__ uint32_t smem_u32(const void* p) {
    uint32_t a;
    asm("{ .reg .u64 t; cvta.to.shared.u64 t, %1; cvt.u32.u64 %0, t; }" : "=r"(a) : "l"(p));
    return a;
}

__device__ __forceinline__ void ldsm4(uint32_t r[4], uint32_t addr) {
    asm volatile("ldmatrix.sync.aligned.m8n8.x4.shared.b16 {%0,%1,%2,%3}, [%4];"
                 : "=r"(r[0]), "=r"(r[1]), "=r"(r[2]), "=r"(r[3]) : "r"(addr));
}

__device__ __forceinline__ void mma_bf16(float d[4], const uint32_t a[4],
                                         uint32_t b0, uint32_t b1) {
    asm volatile(
        "mma.sync.aligned.m16n8k16.row.col.f32.bf16.bf16.f32 "
        "{%0,%1,%2,%3}, {%4,%5,%6,%7}, {%8,%9}, {%0,%1,%2,%3};"
        : "+f"(d[0]), "+f"(d[1]), "+f"(d[2]), "+f"(d[3])
        : "r"(a[0]), "r"(a[1]), "r"(a[2]), "r"(a[3]), "r"(b0), "r"(b1));
}

#define CP_ASYNC16(sm, g) \
    asm volatile("cp.async.cg.shared.global [%0], [%1], 16;" :: "r"(sm), "l"(g))
#define CP_COMMIT()  asm volatile("cp.async.commit_group;" ::: "memory")
#define CP_WAIT(n)   asm volatile("cp.async.wait_group %0;" :: "n"(n) : "memory")

// Fast accurate tanh: 1 - 2/(exp2(2*log2e*x)+1). MUFU ex2/rcp, err ~1e-6.
__device__ __forceinline__ float fast_tanh(float x) {
    float e, r;
    asm("ex2.approx.f32 %0, %1;" : "=f"(e) : "f"(x * 2.8853900817779268f));
    asm("rcp.approx.f32 %0, %1;" : "=f"(r) : "f"(e + 1.0f));
    return fmaf(-2.0f, r, 1.0f);
}

// ---------------------------------------------------------------------------
// Kernel A: convert keys & W2 fp32 -> (hi, lo) bf16 split
// ---------------------------------------------------------------------------
__global__ void __launch_bounds__(256) convert_kernel(const float* __restrict__ keys,
                                                      const float* __restrict__ W2) {
    int blk = blockIdx.x;
    const float4* src;
    uint2 *dhi, *dlo;
    size_t base;
    if (blk < 2048) {
        src = (const float4*)keys;
        dhi = (uint2*)g_keys_hi; dlo = (uint2*)g_keys_lo;
        base = (size_t)blk * 4096;
    } else {
        src = (const float4*)W2;
        dhi = (uint2*)g_w2_hi; dlo = (uint2*)g_w2_lo;
        base = (size_t)(blk - 2048) * 4096;
    }
#pragma unroll 4
    for (int i = 0; i < 16; i++) {
        size_t idx = base + (size_t)i * 256 + threadIdx.x;
        float4 x = src[idx];
        __nv_bfloat162 h01, h23, l01, l23;
        h01.x = __float2bfloat16(x.x); h01.y = __float2bfloat16(x.y);
        h23.x = __float2bfloat16(x.z); h23.y = __float2bfloat16(x.w);
        l01.x = __float2bfloat16(x.x - __bfloat162float(h01.x));
        l01.y = __float2bfloat16(x.y - __bfloat162float(h01.y));
        l23.x = __float2bfloat16(x.z - __bfloat162float(h23.x));
        l23.y = __float2bfloat16(x.w - __bfloat162float(h23.y));
        uint2 hv, lv;
        hv.x = *reinterpret_cast<unsigned*>(&h01);
        hv.y = *reinterpret_cast<unsigned*>(&h23);
        lv.x = *reinterpret_cast<unsigned*>(&l01);
        lv.y = *reinterpret_cast<unsigned*>(&l23);
        dhi[idx] = hv;
        dlo[idx] = lv;
    }
}

// ---------------------------------------------------------------------------
// Kernel B: w1q[b][a] = query[b] . W1[a]
// ---------------------------------------------------------------------------
__global__ void __launch_bounds__(128) w1q_kernel(const float* __restrict__ query,
                                                  const float* __restrict__ W1) {
    int a = blockIdx.x * 128 + threadIdx.x;
    int b = blockIdx.y;
    const float4* w = (const float4*)(W1 + (size_t)a * DQ);
    const float4* q = (const float4*)(query + (size_t)b * DQ);
    float acc = 0.f;
#pragma unroll 8
    for (int d = 0; d < DQ / 4; d++) {
        float4 wv = w[d], qv = q[d];
        acc += wv.x * qv.x + wv.y * qv.y + wv.z * qv.z + wv.w * qv.w;
    }
    g_w1q[b * DQ + a] = acc;
}

// ---------------------------------------------------------------------------
// Kernel C: bf16x3 GEMM via mma.sync(m16n8k16) + fused tanh/v epilogue.
// CTA tile 128(M) x 256(N), BK=32, 512 threads / 16 warps, warp tile 64x32.
// 3-pass product structure (hh, lh, hl) -> same-acc MMA reuse distance 16.
// SMEM 8x8-block-major (128B per 8x8 bf16 block) -> conflict-free ldmatrix.
// Grid: (2 n-tiles, 512 m-tiles).
// ---------------------------------------------------------------------------
#define AHI 0
#define ALO 8192
#define BHI 16384
#define BLO 32768
#define STAGE_B 49152
#define SMEM_TOTAL (2 * STAGE_B)

__global__ void __launch_bounds__(512, 1) gemm_kernel(const float* __restrict__ v) {
    extern __shared__ char smem[];
    const uint32_t sb = smem_u32(smem);
    const int tid = threadIdx.x;
    const int wid = tid >> 5, lane = tid & 31;
    const int mw  = wid & 1;          // 0..1  -> 64 M rows
    const int nwp = wid >> 1;         // 0..7  -> 32 N cols
    const int row0 = blockIdx.y * 128;
    const int col0 = blockIdx.x * 256;

    // ldmatrix lane address: matrices [r0k0, r8k0, r0k8, r8k8]
    const uint32_t laneA = (((lane & 15) >> 3) << 9) + ((lane >> 4) << 7) + ((lane & 7) << 4);

    float acc[4][4][4];               // [mt][n8][frag]
#pragma unroll
    for (int i = 0; i < 4; i++)
#pragma unroll
        for (int j = 0; j < 4; j++)
#pragma unroll
            for (int k = 0; k < 4; k++) acc[i][j][k] = 0.f;

    // ---- async load of one BK=32 chunk into stage s (512 threads) ----
    auto load_chunk = [&](int kc, int s) {
        const uint32_t sbase = sb + s * STAGE_B;
        const size_t kof = (size_t)kc * 32;
        {   // A: 128 rows x 4 kb -> 512 chunks, 1 per thread per version
            int row = tid >> 2, kb = tid & 3;
            size_t gi = (size_t)(row0 + row) * DQ + kof + kb * 8;
            uint32_t sm = sbase + ((row >> 3) * 4 + kb) * 128 + ((row & 7) << 4);
            CP_ASYNC16(sm + AHI, g_keys_hi + gi);
            CP_ASYNC16(sm + ALO, g_keys_lo + gi);
        }
#pragma unroll
        for (int i = 0; i < 2; i++) {  // B: 256 rows x 4 kb -> 1024 chunks, 2/thread
            int u = tid + i * 512;
            int row = u >> 2, kb = u & 3;
            size_t gi = (size_t)(col0 + row) * DQ + kof + kb * 8;
            uint32_t sm = sbase + ((row >> 3) * 4 + kb) * 128 + ((row & 7) << 4);
            CP_ASYNC16(sm + BHI, g_w2_hi + gi);
            CP_ASYNC16(sm + BLO, g_w2_lo + gi);
        }
    };

    load_chunk(0, 0);
    CP_COMMIT();

#pragma unroll 1
    for (int c = 0; c < 16; c++) {
        if (c < 15) {
            load_chunk(c + 1, (c + 1) & 1);
            CP_COMMIT();
            CP_WAIT(1);
        } else {
            CP_WAIT(0);
        }
        __syncthreads();

        const uint32_t stg = sb + (c & 1) * STAGE_B;
#pragma unroll
        for (int kt = 0; kt < 2; kt++) {
            // warp bases: A rows mw*64 (= 8 row-blocks * 512B), B rows nwp*32
            const uint32_t abase = stg + laneA + mw * 4096 + kt * 256;
            const uint32_t bbase = stg + laneA + nwp * 2048 + kt * 256;

            uint32_t ah[4][4], bh[2][4];
#pragma unroll
            for (int mt = 0; mt < 4; mt++) ldsm4(ah[mt], abase + AHI + mt * 1024);
#pragma unroll
            for (int pb = 0; pb < 2; pb++) ldsm4(bh[pb], bbase + BHI + pb * 1024);

            // pass 1: hi*hi — 16 independent MMAs
#pragma unroll
            for (int mt = 0; mt < 4; mt++)
#pragma unroll
                for (int pb = 0; pb < 2; pb++) {
                    mma_bf16(acc[mt][2 * pb],     ah[mt], bh[pb][0], bh[pb][2]);
                    mma_bf16(acc[mt][2 * pb + 1], ah[mt], bh[pb][1], bh[pb][3]);
                }

            // pass 2: lo*hi
            uint32_t al[4][4];
#pragma unroll
            for (int mt = 0; mt < 4; mt++) ldsm4(al[mt], abase + ALO + mt * 1024);
#pragma unroll
            for (int mt = 0; mt < 4; mt++)
#pragma unroll
                for (int pb = 0; pb < 2; pb++) {
                    mma_bf16(acc[mt][2 * pb],     al[mt], bh[pb][0], bh[pb][2]);
                    mma_bf16(acc[mt][2 * pb + 1], al[mt], bh[pb][1], bh[pb][3]);
                }

            // pass 3: hi*lo
            uint32_t bl[2][4];
#pragma unroll
            for (int pb = 0; pb < 2; pb++) ldsm4(bl[pb], bbase + BLO + pb * 1024);
#pragma unroll
            for (int mt = 0; mt < 4; mt++)
#pragma unroll
                for (int pb = 0; pb < 2; pb++) {
                    mma_bf16(acc[mt][2 * pb],     ah[mt], bl[pb][0], bl[pb][2]);
                    mma_bf16(acc[mt][2 * pb + 1], ah[mt], bl[pb][1], bl[pb][3]);
                }
        }
        __syncthreads();
    }

    // ---- epilogue: tanh(acc + w1q) * v, reduce over 256-wide N tile ----
    const int b_idx = row0 >> 11;
    const int q = lane >> 2;
    float* red = (float*)smem;        // 8 (nwp) x 128 rows

#pragma unroll
    for (int mt = 0; mt < 4; mt++) {
        float p0 = 0.f, p1 = 0.f;
#pragma unroll
        for (int n8 = 0; n8 < 4; n8++) {
            int cg = col0 + nwp * 32 + n8 * 8 + (lane & 3) * 2;
            float2 w1 = *(const float2*)(g_w1q + b_idx * DQ + cg);
            float2 vv = *(const float2*)(v + cg);
            float* d = acc[mt][n8];
            p0 += fast_tanh(d[0] + w1.x) * vv.x + fast_tanh(d[1] + w1.y) * vv.y;
            p1 += fast_tanh(d[2] + w1.x) * vv.x + fast_tanh(d[3] + w1.y) * vv.y;
        }
        p0 += __shfl_xor_sync(0xffffffff, p0, 1);
        p0 += __shfl_xor_sync(0xffffffff, p0, 2);
        p1 += __shfl_xor_sync(0xffffffff, p1, 1);
        p1 += __shfl_xor_sync(0xffffffff, p1, 2);
        if ((lane & 3) == 0) {
            int r = mw * 64 + mt * 16 + q;
            red[nwp * 128 + r]     = p0;
            red[nwp * 128 + r + 8] = p1;
        }
    }
    __syncthreads();
    if (tid < 128) {
        float s = 0.f;
#pragma unroll
        for (int w = 0; w < 8; w++) s += red[w * 128 + tid];
        g_partial[blockIdx.x][row0 + tid] = s;
    }
}

// ---------------------------------------------------------------------------
// Kernel D: masked softmax (mask int32). One block per batch row.
// ---------------------------------------------------------------------------
__global__ void __launch_bounds__(256) softmax_kernel(const int* __restrict__ mask,
                                                      float* __restrict__ out) {
    const int b = blockIdx.x, tid = threadIdx.x;
    __shared__ float red[256];

    float vals[8];
    float mx = -INFINITY;
#pragma unroll
    for (int t = 0; t < 8; t++) {
        int gi = b * SDIM + tid + t * 256;
        float sc = g_partial[0][gi] + g_partial[1][gi];
        sc = mask[gi] ? sc : -INFINITY;
        vals[t] = sc;
        mx = fmaxf(mx, sc);
    }
    red[tid] = mx;
    __syncthreads();
    for (int o = 128; o; o >>= 1) {
        if (tid < o) red[tid] = fmaxf(red[tid], red[tid + o]);
        __syncthreads();
    }
    mx = red[0];
    __syncthreads();

    float sum = 0.f;
#pragma unroll
    for (int t = 0; t < 8; t++) {
        vals[t] = expf(vals[t] - mx);
        sum += vals[t];
    }
    red[tid] = sum;
    __syncthreads();
    for (int o = 128; o; o >>= 1) {
        if (tid < o) red[tid] += red[tid + o];
        __syncthreads();
    }
    float inv = 1.f / red[0];
#pragma unroll
    for (int t = 0; t < 8; t++) out[b * SDIM + tid + t * 256] = vals[t] * inv;
}

// ---------------------------------------------------------------------------
// Launch
// ---------------------------------------------------------------------------
extern "C" void kernel_launch(void* const* d_in, const int* in_sizes, int n_in,
                              void* d_out, int out_size) {
    const float* query = (const float*)d_in[0];
    const float* keys  = (const float*)d_in[1];
    const int*   mask  = (const int*)d_in[2];
    const float* W1    = (const float*)d_in[3];
    const float* W2    = (const float*)d_in[4];
    const float* v     = (const float*)d_in[5];
    float*       out   = (float*)d_out;

    static bool attr_set = false;
    if (!attr_set) {
        cudaFuncSetAttribute(gemm_kernel, cudaFuncAttributeMaxDynamicSharedMemorySize,
                             SMEM_TOTAL);
        attr_set = true;
    }

    convert_kernel<<<2064, 256>>>(keys, W2);
    w1q_kernel<<<dim3(4, BQ), 128>>>(query, W1);
    gemm_kernel<<<dim3(2, 512), 512, SMEM_TOTAL>>>(v);
    softmax_kernel<<<BQ, 256>>>(mask, out);
}

// round 9
// speedup vs baseline: 1.6657x; 1.6657x over previous
#include <cuda_runtime.h>
#include <cuda_fp16.h>
#include <cstdint>
#include <math.h>

// ---------------------------------------------------------------------------
// Problem dims
// ---------------------------------------------------------------------------
#define BQ   32
#define SDIM 2048
#define DQ   512
#define MTOT (BQ * SDIM)          // 65536
#define MPAD (MTOT + 256)         // room for tail-tile padding rows

// ---------------------------------------------------------------------------
// Device scratch (static only)
// ---------------------------------------------------------------------------
__device__ __align__(256) __half g_ka_hi[(size_t)MPAD * DQ];  // compact keys hi
__device__ __align__(256) __half g_ka_lo[(size_t)MPAD * DQ];  // compact keys lo
__device__ __align__(256) __half g_w2h[DQ * DQ];
__device__ __align__(256) __half g_w2l[DQ * DQ];
__device__ float g_w1q[BQ * DQ];
__device__ float g_partial[2][MPAD];
__device__ int   g_rowmap[MPAD];
__device__ int   g_blockcnt[256];
__device__ int   g_blockoff[256];
__device__ int   g_count;
__device__ int   g_ntiles;

// ---------------------------------------------------------------------------
// Helpers
// ---------------------------------------------------------------------------
__device__ __forceinline__ uint32_t smem_u32(const void* p) {
    uint32_t a;
    asm("{ .reg .u64 t; cvta.to.shared.u64 t, %1; cvt.u32.u64 %0, t; }" : "=r"(a) : "l"(p));
    return a;
}

__device__ __forceinline__ void ldsm4(uint32_t r[4], uint32_t addr) {
    asm volatile("ldmatrix.sync.aligned.m8n8.x4.shared.b16 {%0,%1,%2,%3}, [%4];"
                 : "=r"(r[0]), "=r"(r[1]), "=r"(r[2]), "=r"(r[3]) : "r"(addr));
}

__device__ __forceinline__ void mma_f16(float d[4], const uint32_t a[4],
                                        uint32_t b0, uint32_t b1) {
    asm volatile(
        "mma.sync.aligned.m16n8k16.row.col.f32.f16.f16.f32 "
        "{%0,%1,%2,%3}, {%4,%5,%6,%7}, {%8,%9}, {%0,%1,%2,%3};"
        : "+f"(d[0]), "+f"(d[1]), "+f"(d[2]), "+f"(d[3])
        : "r"(a[0]), "r"(a[1]), "r"(a[2]), "r"(a[3]), "r"(b0), "r"(b1));
}

#define CP_ASYNC16(sm, g) \
    asm volatile("cp.async.cg.shared.global [%0], [%1], 16;" :: "r"(sm), "l"(g))
#define CP_COMMIT()  asm volatile("cp.async.commit_group;" ::: "memory")
#define CP_WAIT(n)   asm volatile("cp.async.wait_group %0;" :: "n"(n) : "memory")

// Fast accurate tanh: 1 - 2/(exp2(2*log2e*x)+1). MUFU ex2/rcp, err ~1e-6.
__device__ __forceinline__ float fast_tanh(float x) {
    float e, r;
    asm("ex2.approx.f32 %0, %1;" : "=f"(e) : "f"(x * 2.8853900817779268f));
    asm("rcp.approx.f32 %0, %1;" : "=f"(r) : "f"(e + 1.0f));
    return fmaf(-2.0f, r, 1.0f);
}

// ---------------------------------------------------------------------------
// K0: per-256-block mask popcount
// ---------------------------------------------------------------------------
__global__ void __launch_bounds__(256) mask_count(const int* __restrict__ mask) {
    int t = threadIdx.x, b = blockIdx.x;
    int m = mask[b * 256 + t] != 0;
    unsigned bal = __ballot_sync(0xffffffffu, m);
    __shared__ int ws[8];
    if ((t & 31) == 0) ws[t >> 5] = __popc(bal);
    __syncthreads();
    if (t == 0) {
        int s = 0;
#pragma unroll
        for (int i = 0; i < 8; i++) s += ws[i];
        g_blockcnt[b] = s;
    }
}

// ---------------------------------------------------------------------------
// K1: scan 256 block counts, publish offsets/count/ntiles, fill padding map
// ---------------------------------------------------------------------------
__global__ void __launch_bounds__(256) mask_scan() {
    __shared__ int sh[256];
    int t = threadIdx.x;
    int v = g_blockcnt[t];
    sh[t] = v;
    __syncthreads();
    for (int o = 1; o < 256; o <<= 1) {
        int x = (t >= o) ? sh[t - o] : 0;
        __syncthreads();
        sh[t] += x;
        __syncthreads();
    }
    g_blockoff[t] = sh[t] - v;
    int total = sh[255];
    if (t == 0) { g_count = total; g_ntiles = (total + 127) >> 7; }
    g_rowmap[total + t] = MTOT + t;   // padding rows -> dump zone
}

// ---------------------------------------------------------------------------
// K2: scatter unmasked original row indices into g_rowmap (stable order)
// ---------------------------------------------------------------------------
__global__ void __launch_bounds__(256) mask_scatter(const int* __restrict__ mask) {
    int t = threadIdx.x, b = blockIdx.x, lane = t & 31, w = t >> 5;
    int m = mask[b * 256 + t] != 0;
    unsigned bal = __ballot_sync(0xffffffffu, m);
    __shared__ int ws[8];
    if (lane == 0) ws[w] = __popc(bal);
    __syncthreads();
    int wb = 0;
    for (int i = 0; i < w; i++) wb += ws[i];
    int rank = g_blockoff[b] + wb + __popc(bal & ((1u << lane) - 1u));
    if (m) g_rowmap[rank] = b * 256 + t;
}

// ---------------------------------------------------------------------------
// K3: compact-convert keys rows (fp32 -> fp16 hi/lo). One row per block iter.
// ---------------------------------------------------------------------------
__global__ void __launch_bounds__(256) convert_keys(const float* __restrict__ keys) {
    const int cnt = g_count;
    const int lim = ((cnt + 127) >> 7) << 7;
    const int t = threadIdx.x;
    for (int r = blockIdx.x; r < lim; r += 256) {
        __half2 h, l;
        if (r < cnt) {
            int orig = g_rowmap[r];
            float2 x = ((const float2*)(keys + (size_t)orig * DQ))[t];
            h = __floats2half2_rn(x.x, x.y);
            float2 hr = __half22float2(h);
            l = __floats2half2_rn(x.x - hr.x, x.y - hr.y);
        } else {
            h = __float2half2_rn(0.f);
            l = h;
        }
        ((__half2*)g_ka_hi)[(size_t)r * 256 + t] = h;
        ((__half2*)g_ka_lo)[(size_t)r * 256 + t] = l;
    }
}

// ---------------------------------------------------------------------------
// K3b: convert W2 (fp32 -> fp16 hi/lo). One row per block.
// ---------------------------------------------------------------------------
__global__ void __launch_bounds__(256) convert_w2(const float* __restrict__ W2) {
    int r = blockIdx.x, t = threadIdx.x;
    float2 x = ((const float2*)(W2 + (size_t)r * DQ))[t];
    __half2 h = __floats2half2_rn(x.x, x.y);
    float2 hr = __half22float2(h);
    __half2 l = __floats2half2_rn(x.x - hr.x, x.y - hr.y);
    ((__half2*)g_w2h)[r * 256 + t] = h;
    ((__half2*)g_w2l)[r * 256 + t] = l;
}

// ---------------------------------------------------------------------------
// K4: w1q[b][a] = query[b] . W1[a]
// ---------------------------------------------------------------------------
__global__ void __launch_bounds__(128) w1q_kernel(const float* __restrict__ query,
                                                  const float* __restrict__ W1) {
    int a = blockIdx.x * 128 + threadIdx.x;
    int b = blockIdx.y;
    const float4* w = (const float4*)(W1 + (size_t)a * DQ);
    const float4* q = (const float4*)(query + (size_t)b * DQ);
    float acc = 0.f;
#pragma unroll 8
    for (int d = 0; d < DQ / 4; d++) {
        float4 wv = w[d], qv = q[d];
        acc += wv.x * qv.x + wv.y * qv.y + wv.z * qv.z + wv.w * qv.w;
    }
    g_w1q[b * DQ + a] = acc;
}

// ---------------------------------------------------------------------------
// K5: fp16x2 split GEMM over compacted rows + fused tanh/v epilogue.
// CTA tile 128(M') x 256(N), BK=32, 512 threads / 16 warps, warp tile 64x32.
// Terms: ah*bh + al*bh (dropped a*bl ~ 2^-11 -> score err ~3e-4).
// SMEM 8x8-block-major (128B per 8x8 fp16 block) -> conflict-free ldmatrix.
// Grid (2 n-tiles, 512 m-tiles); tiles beyond g_ntiles early-exit.
// ---------------------------------------------------------------------------
#define AHI 0
#define ALO 8192
#define BHI 16384
#define STAGE_B 32768
#define SMEM_TOTAL (2 * STAGE_B)

__global__ void __launch_bounds__(512, 1) gemm_kernel(const float* __restrict__ v) {
    if ((int)blockIdx.y >= g_ntiles) return;

    extern __shared__ char smem[];
    const uint32_t sb = smem_u32(smem);
    const int tid = threadIdx.x;
    const int wid = tid >> 5, lane = tid & 31;
    const int mw  = wid & 1;          // 0..1  -> 64 M rows
    const int nwp = wid >> 1;         // 0..7  -> 32 N cols
    const int row0 = blockIdx.y * 128;     // compact-row base
    const int col0 = blockIdx.x * 256;

    const uint32_t laneA = (((lane & 15) >> 3) << 9) + ((lane >> 4) << 7) + ((lane & 7) << 4);

    float acc[4][4][4];
#pragma unroll
    for (int i = 0; i < 4; i++)
#pragma unroll
        for (int j = 0; j < 4; j++)
#pragma unroll
            for (int k = 0; k < 4; k++) acc[i][j][k] = 0.f;

    auto load_chunk = [&](int kc, int s) {
        const uint32_t sbase = sb + s * STAGE_B;
        const size_t kof = (size_t)kc * 32;
        {   // A: 128 rows x 4 16B-chunks (hi + lo), 1 each per thread
            int row = tid >> 2, kb = tid & 3;
            size_t gi = (size_t)(row0 + row) * DQ + kof + kb * 8;
            uint32_t sm = sbase + ((row >> 3) * 4 + kb) * 128 + ((row & 7) << 4);
            CP_ASYNC16(sm + AHI, g_ka_hi + gi);
            CP_ASYNC16(sm + ALO, g_ka_lo + gi);
        }
#pragma unroll
        for (int i = 0; i < 2; i++) {  // B: 256 rows x 4 chunks, 2 per thread
            int u = tid + i * 512;
            int row = u >> 2, kb = u & 3;
            size_t gi = (size_t)(col0 + row) * DQ + kof + kb * 8;
            uint32_t sm = sbase + ((row >> 3) * 4 + kb) * 128 + ((row & 7) << 4);
            CP_ASYNC16(sm + BHI, g_w2h + gi);
        }
    };

    load_chunk(0, 0);
    CP_COMMIT();

#pragma unroll 1
    for (int c = 0; c < 16; c++) {
        if (c < 15) {
            load_chunk(c + 1, (c + 1) & 1);
            CP_COMMIT();
            CP_WAIT(1);
        } else {
            CP_WAIT(0);
        }
        __syncthreads();

        const uint32_t stg = sb + (c & 1) * STAGE_B;
#pragma unroll
        for (int kt = 0; kt < 2; kt++) {
            const uint32_t abase = stg + laneA + mw * 4096 + kt * 256;
            const uint32_t bbase = stg + laneA + nwp * 2048 + kt * 256;

            uint32_t ah[4][4], bh[2][4];
#pragma unroll
            for (int mt = 0; mt < 4; mt++) ldsm4(ah[mt], abase + AHI + mt * 1024);
#pragma unroll
            for (int pb = 0; pb < 2; pb++) ldsm4(bh[pb], bbase + BHI + pb * 1024);

            // pass 1: ah*bh — 16 independent MMAs
#pragma unroll
            for (int mt = 0; mt < 4; mt++)
#pragma unroll
                for (int pb = 0; pb < 2; pb++) {
                    mma_f16(acc[mt][2 * pb],     ah[mt], bh[pb][0], bh[pb][2]);
                    mma_f16(acc[mt][2 * pb + 1], ah[mt], bh[pb][1], bh[pb][3]);
                }

            // pass 2: al*bh
            uint32_t al[4][4];
#pragma unroll
            for (int mt = 0; mt < 4; mt++) ldsm4(al[mt], abase + ALO + mt * 1024);
#pragma unroll
            for (int mt = 0; mt < 4; mt++)
#pragma unroll
                for (int pb = 0; pb < 2; pb++) {
                    mma_f16(acc[mt][2 * pb],     al[mt], bh[pb][0], bh[pb][2]);
                    mma_f16(acc[mt][2 * pb + 1], al[mt], bh[pb][1], bh[pb][3]);
                }
        }
        __syncthreads();
    }

    // ---- epilogue: tanh(acc + w1q) * v, reduce N, scatter via rowmap ----
    const int q = lane >> 2;
    float* red = (float*)smem;

#pragma unroll
    for (int mt = 0; mt < 4; mt++) {
        // b index per row needed: rows in this tile may span batches? No:
        // compact rows come from sorted original order, but one tile CAN span
        // a batch boundary -> w1q must be looked up per row. Handle via per-row
        // orig: defer w1q add? Instead: rows here are compact; we need
        // w1q[b(orig)][col]. Load per accumulator row.
        int r_lo = row0 + mw * 64 + mt * 16 + q;        // compact row of d[0],d[1]
        int r_hi = r_lo + 8;                            // compact row of d[2],d[3]
        int b_lo = g_rowmap[r_lo] >> 11;                // orig/2048 (dump rows -> >=32, clamp)
        int b_hi = g_rowmap[r_hi] >> 11;
        if (b_lo > BQ - 1) b_lo = BQ - 1;
        if (b_hi > BQ - 1) b_hi = BQ - 1;
        float p0 = 0.f, p1 = 0.f;
#pragma unroll
        for (int n8 = 0; n8 < 4; n8++) {
            int cg = col0 + nwp * 32 + n8 * 8 + (lane & 3) * 2;
            float2 w1a = *(const float2*)(g_w1q + b_lo * DQ + cg);
            float2 w1b = *(const float2*)(g_w1q + b_hi * DQ + cg);
            float2 vv = *(const float2*)(v + cg);
            float* d = acc[mt][n8];
            p0 += fast_tanh(d[0] + w1a.x) * vv.x + fast_tanh(d[1] + w1a.y) * vv.y;
            p1 += fast_tanh(d[2] + w1b.x) * vv.x + fast_tanh(d[3] + w1b.y) * vv.y;
        }
        p0 += __shfl_xor_sync(0xffffffff, p0, 1);
        p0 += __shfl_xor_sync(0xffffffff, p0, 2);
        p1 += __shfl_xor_sync(0xffffffff, p1, 1);
        p1 += __shfl_xor_sync(0xffffffff, p1, 2);
        if ((lane & 3) == 0) {
            int r = mw * 64 + mt * 16 + q;
            red[nwp * 128 + r]     = p0;
            red[nwp * 128 + r + 8] = p1;
        }
    }
    __syncthreads();
    if (tid < 128) {
        float s = 0.f;
#pragma unroll
        for (int w = 0; w < 8; w++) s += red[w * 128 + tid];
        g_partial[blockIdx.x][g_rowmap[row0 + tid]] = s;
    }
}

// ---------------------------------------------------------------------------
// K6: masked softmax (mask int32). One block per batch row.
// ---------------------------------------------------------------------------
__global__ void __launch_bounds__(256) softmax_kernel(const int* __restrict__ mask,
                                                      float* __restrict__ out) {
    const int b = blockIdx.x, tid = threadIdx.x;
    __shared__ float red[256];

    float vals[8];
    float mx = -INFINITY;
#pragma unroll
    for (int t = 0; t < 8; t++) {
        int gi = b * SDIM + tid + t * 256;
        float sc = g_partial[0][gi] + g_partial[1][gi];
        sc = mask[gi] ? sc : -INFINITY;
        vals[t] = sc;
        mx = fmaxf(mx, sc);
    }
    red[tid] = mx;
    __syncthreads();
    for (int o = 128; o; o >>= 1) {
        if (tid < o) red[tid] = fmaxf(red[tid], red[tid + o]);
        __syncthreads();
    }
    mx = red[0];
    __syncthreads();

    float sum = 0.f;
#pragma unroll
    for (int t = 0; t < 8; t++) {
        vals[t] = expf(vals[t] - mx);
        sum += vals[t];
    }
    red[tid] = sum;
    __syncthreads();
    for (int o = 128; o; o >>= 1) {
        if (tid < o) red[tid] += red[tid + o];
        __syncthreads();
    }
    float inv = 1.f / red[0];
#pragma unroll
    for (int t = 0; t < 8; t++) out[b * SDIM + tid + t * 256] = vals[t] * inv;
}

// ---------------------------------------------------------------------------
// Launch
// ---------------------------------------------------------------------------
extern "C" void kernel_launch(void* const* d_in, const int* in_sizes, int n_in,
                              void* d_out, int out_size) {
    const float* query = (const float*)d_in[0];
    const float* keys  = (const float*)d_in[1];
    const int*   mask  = (const int*)d_in[2];
    const float* W1    = (const float*)d_in[3];
    const float* W2    = (const float*)d_in[4];
    const float* v     = (const float*)d_in[5];
    float*       out   = (float*)d_out;

    static bool attr_set = false;
    if (!attr_set) {
        cudaFuncSetAttribute(gemm_kernel, cudaFuncAttributeMaxDynamicSharedMemorySize,
                             SMEM_TOTAL);
        attr_set = true;
    }

    mask_count<<<256, 256>>>(mask);
    mask_scan<<<1, 256>>>();
    mask_scatter<<<256, 256>>>(mask);
    convert_keys<<<256, 256>>>(keys);
    convert_w2<<<512, 256>>>(W2);
    w1q_kernel<<<dim3(4, BQ), 128>>>(query, W1);
    gemm_kernel<<<dim3(2, 512), 512, SMEM_TOTAL>>>(v);
    softmax_kernel<<<BQ, 256>>>(mask, out);
}

// round 10
// speedup vs baseline: 2.7566x; 1.6550x over previous
#include <cuda_runtime.h>
#include <cuda_fp16.h>
#include <cstdint>
#include <math.h>

// ---------------------------------------------------------------------------
// Problem dims
// ---------------------------------------------------------------------------
#define BQ   32
#define SDIM 2048
#define DQ   512
#define MTOT (BQ * SDIM)          // 65536
#define MPAD (MTOT + 256)

// ---------------------------------------------------------------------------
// Device scratch (static only)
// ---------------------------------------------------------------------------
__device__ __align__(256) __half g_w2h[DQ * DQ];
__device__ float g_w1q[BQ * DQ];
__device__ float g_partial[2][MPAD];
__device__ int   g_rowmap[MPAD];
__device__ int   g_blockcnt[256];
__device__ int   g_blockoff[256];
__device__ int   g_count;
__device__ int   g_ntiles;

// ---------------------------------------------------------------------------
// Helpers
// ---------------------------------------------------------------------------
__device__ __forceinline__ uint32_t smem_u32(const void* p) {
    uint32_t a;
    asm("{ .reg .u64 t; cvta.to.shared.u64 t, %1; cvt.u32.u64 %0, t; }" : "=r"(a) : "l"(p));
    return a;
}

__device__ __forceinline__ void ldsm4(uint32_t r[4], uint32_t addr) {
    asm volatile("ldmatrix.sync.aligned.m8n8.x4.shared.b16 {%0,%1,%2,%3}, [%4];"
                 : "=r"(r[0]), "=r"(r[1]), "=r"(r[2]), "=r"(r[3]) : "r"(addr));
}

__device__ __forceinline__ void mma_f16(float d[4], const uint32_t a[4],
                                        uint32_t b0, uint32_t b1) {
    asm volatile(
        "mma.sync.aligned.m16n8k16.row.col.f32.f16.f16.f32 "
        "{%0,%1,%2,%3}, {%4,%5,%6,%7}, {%8,%9}, {%0,%1,%2,%3};"
        : "+f"(d[0]), "+f"(d[1]), "+f"(d[2]), "+f"(d[3])
        : "r"(a[0]), "r"(a[1]), "r"(a[2]), "r"(a[3]), "r"(b0), "r"(b1));
}

#define CP_ASYNC16(sm, g) \
    asm volatile("cp.async.cg.shared.global [%0], [%1], 16;" :: "r"(sm), "l"(g))
#define CP_COMMIT()  asm volatile("cp.async.commit_group;" ::: "memory")
#define CP_WAIT0()   asm volatile("cp.async.wait_group 0;" ::: "memory")

#define STS128(addr, r0, r1, r2, r3) \
    asm volatile("st.shared.v4.b32 [%0], {%1,%2,%3,%4};" \
                 :: "r"(addr), "r"(r0), "r"(r1), "r"(r2), "r"(r3) : "memory")

// Fast accurate tanh: 1 - 2/(exp2(2*log2e*x)+1). MUFU ex2/rcp, err ~1e-6.
__device__ __forceinline__ float fast_tanh(float x) {
    float e, r;
    asm("ex2.approx.f32 %0, %1;" : "=f"(e) : "f"(x * 2.8853900817779268f));
    asm("rcp.approx.f32 %0, %1;" : "=f"(r) : "f"(e + 1.0f));
    return fmaf(-2.0f, r, 1.0f);
}

// ---------------------------------------------------------------------------
// K0: per-256-block mask popcount
// ---------------------------------------------------------------------------
__global__ void __launch_bounds__(256) mask_count(const int* __restrict__ mask) {
    int t = threadIdx.x, b = blockIdx.x;
    int m = mask[b * 256 + t] != 0;
    unsigned bal = __ballot_sync(0xffffffffu, m);
    __shared__ int ws[8];
    if ((t & 31) == 0) ws[t >> 5] = __popc(bal);
    __syncthreads();
    if (t == 0) {
        int s = 0;
#pragma unroll
        for (int i = 0; i < 8; i++) s += ws[i];
        g_blockcnt[b] = s;
    }
}

// ---------------------------------------------------------------------------
// K1: scan block counts, publish offsets/count/ntiles, fill padding map
// ---------------------------------------------------------------------------
__global__ void __launch_bounds__(256) mask_scan() {
    __shared__ int sh[256];
    int t = threadIdx.x;
    int v = g_blockcnt[t];
    sh[t] = v;
    __syncthreads();
    for (int o = 1; o < 256; o <<= 1) {
        int x = (t >= o) ? sh[t - o] : 0;
        __syncthreads();
        sh[t] += x;
        __syncthreads();
    }
    g_blockoff[t] = sh[t] - v;
    int total = sh[255];
    if (t == 0) { g_count = total; g_ntiles = (total + 127) >> 7; }
    g_rowmap[total + t] = MTOT + t;   // padding rows -> dump zone
}

// ---------------------------------------------------------------------------
// K2: scatter unmasked original row indices into g_rowmap (stable order)
// ---------------------------------------------------------------------------
__global__ void __launch_bounds__(256) mask_scatter(const int* __restrict__ mask) {
    int t = threadIdx.x, b = blockIdx.x, lane = t & 31, w = t >> 5;
    int m = mask[b * 256 + t] != 0;
    unsigned bal = __ballot_sync(0xffffffffu, m);
    __shared__ int ws[8];
    if (lane == 0) ws[w] = __popc(bal);
    __syncthreads();
    int wb = 0;
    for (int i = 0; i < w; i++) wb += ws[i];
    int rank = g_blockoff[b] + wb + __popc(bal & ((1u << lane) - 1u));
    if (m) g_rowmap[rank] = b * 256 + t;
}

// ---------------------------------------------------------------------------
// K3: convert W2 (fp32 -> fp16 hi only). One row per block.
// ---------------------------------------------------------------------------
__global__ void __launch_bounds__(256) convert_w2(const float* __restrict__ W2) {
    int r = blockIdx.x, t = threadIdx.x;
    float2 x = ((const float2*)(W2 + (size_t)r * DQ))[t];
    ((__half2*)g_w2h)[r * 256 + t] = __floats2half2_rn(x.x, x.y);
}

// ---------------------------------------------------------------------------
// K4: w1q[b][a] = query[b] . W1[a]
// ---------------------------------------------------------------------------
__global__ void __launch_bounds__(128) w1q_kernel(const float* __restrict__ query,
                                                  const float* __restrict__ W1) {
    int a = blockIdx.x * 128 + threadIdx.x;
    int b = blockIdx.y;
    const float4* w = (const float4*)(W1 + (size_t)a * DQ);
    const float4* q = (const float4*)(query + (size_t)b * DQ);
    float acc = 0.f;
#pragma unroll 8
    for (int d = 0; d < DQ / 4; d++) {
        float4 wv = w[d], qv = q[d];
        acc += wv.x * qv.x + wv.y * qv.y + wv.z * qv.z + wv.w * qv.w;
    }
    g_w1q[b * DQ + a] = acc;
}

// ---------------------------------------------------------------------------
// K5: fused convert + fp16x2 split GEMM over compacted rows + tanh/v epilogue.
// A path: LDG keys fp32 (rowmap gather, hoisted) -> reg split hi/lo -> STS.
// B path: cp.async from pre-converted g_w2h.
// CTA tile 128 x 256, BK=32, 512 threads / 16 warps, warp tile 64x32.
// SMEM 8x8-block-major -> conflict-free ldmatrix. Grid (2, 512), early-exit.
// ---------------------------------------------------------------------------
#define AHI 0
#define ALO 8192
#define BHI 16384
#define STAGE_B 32768
#define SMEM_TOTAL (2 * STAGE_B)

__global__ void __launch_bounds__(512, 1) gemm_kernel(const float* __restrict__ keys,
                                                      const float* __restrict__ v) {
    if ((int)blockIdx.y >= g_ntiles) return;

    extern __shared__ char smem[];
    const uint32_t sb = smem_u32(smem);
    const int tid = threadIdx.x;
    const int wid = tid >> 5, lane = tid & 31;
    const int mw  = wid & 1;
    const int nwp = wid >> 1;
    const int row0 = blockIdx.y * 128;
    const int col0 = blockIdx.x * 256;

    const uint32_t laneA = (((lane & 15) >> 3) << 9) + ((lane >> 4) << 7) + ((lane & 7) << 4);

    // ---- hoisted A-gather address: thread owns (row = tid>>2, kb = tid&3) ----
    const int arow = tid >> 2, akb = tid & 3;
    int orig = g_rowmap[row0 + arow];
    if (orig > MTOT - 1) orig = MTOT - 1;          // padding rows: read valid mem
    const float4* aptr = (const float4*)(keys + (size_t)orig * DQ + akb * 8);
    const uint32_t asts = sb + ((arow >> 3) * 4 + akb) * 128 + ((arow & 7) << 4);

    float acc[4][4][4];
#pragma unroll
    for (int i = 0; i < 4; i++)
#pragma unroll
        for (int j = 0; j < 4; j++)
#pragma unroll
            for (int k = 0; k < 4; k++) acc[i][j][k] = 0.f;

    // load 8 fp32 of chunk c, split -> 4 hi uint32 + 4 lo uint32
    auto loadA = [&](int c, uint32_t h[4], uint32_t l[4]) {
        float4 x0 = aptr[c * 8];
        float4 x1 = aptr[c * 8 + 1];
        float f[8] = {x0.x, x0.y, x0.z, x0.w, x1.x, x1.y, x1.z, x1.w};
#pragma unroll
        for (int i = 0; i < 4; i++) {
            __half2 hh = __floats2half2_rn(f[2 * i], f[2 * i + 1]);
            float2 hf = __half22float2(hh);
            __half2 ll = __floats2half2_rn(f[2 * i] - hf.x, f[2 * i + 1] - hf.y);
            h[i] = *reinterpret_cast<unsigned*>(&hh);
            l[i] = *reinterpret_cast<unsigned*>(&ll);
        }
    };

    auto loadB = [&](int c, int s) {
        const uint32_t sbase = sb + s * STAGE_B;
        const size_t kof = (size_t)c * 32;
#pragma unroll
        for (int i = 0; i < 2; i++) {
            int u = tid + i * 512;
            int row = u >> 2, kb = u & 3;
            size_t gi = (size_t)(col0 + row) * DQ + kof + kb * 8;
            uint32_t sm = sbase + ((row >> 3) * 4 + kb) * 128 + ((row & 7) << 4);
            CP_ASYNC16(sm + BHI, g_w2h + gi);
        }
    };

    uint32_t hA[4], lA[4], hN[4], lN[4];
    loadA(0, hA, lA);
    loadB(0, 0);
    CP_COMMIT();

#pragma unroll 1
    for (int c = 0; c < 16; c++) {
        const int s = c & 1;
        const uint32_t stg = sb + s * STAGE_B;

        CP_WAIT0();                                   // B(c) resident
        STS128(asts + s * STAGE_B + AHI, hA[0], hA[1], hA[2], hA[3]);
        STS128(asts + s * STAGE_B + ALO, lA[0], lA[1], lA[2], lA[3]);
        __syncthreads();                              // orders STS/cp.async vs LDSM

        if (c < 15) {
            loadB(c + 1, s ^ 1);                      // safe: stage s^1 drained at sync
            CP_COMMIT();
            loadA(c + 1, hN, lN);                     // LDG latency hides under MMAs
        }

#pragma unroll
        for (int kt = 0; kt < 2; kt++) {
            const uint32_t abase = stg + laneA + mw * 4096 + kt * 256;
            const uint32_t bbase = stg + laneA + nwp * 2048 + kt * 256;

            uint32_t ah[4][4], bh[2][4];
#pragma unroll
            for (int mt = 0; mt < 4; mt++) ldsm4(ah[mt], abase + AHI + mt * 1024);
#pragma unroll
            for (int pb = 0; pb < 2; pb++) ldsm4(bh[pb], bbase + BHI + pb * 1024);

#pragma unroll
            for (int mt = 0; mt < 4; mt++)
#pragma unroll
                for (int pb = 0; pb < 2; pb++) {
                    mma_f16(acc[mt][2 * pb],     ah[mt], bh[pb][0], bh[pb][2]);
                    mma_f16(acc[mt][2 * pb + 1], ah[mt], bh[pb][1], bh[pb][3]);
                }

            uint32_t al[4][4];
#pragma unroll
            for (int mt = 0; mt < 4; mt++) ldsm4(al[mt], abase + ALO + mt * 1024);
#pragma unroll
            for (int mt = 0; mt < 4; mt++)
#pragma unroll
                for (int pb = 0; pb < 2; pb++) {
                    mma_f16(acc[mt][2 * pb],     al[mt], bh[pb][0], bh[pb][2]);
                    mma_f16(acc[mt][2 * pb + 1], al[mt], bh[pb][1], bh[pb][3]);
                }
        }

#pragma unroll
        for (int i = 0; i < 4; i++) { hA[i] = hN[i]; lA[i] = lN[i]; }
    }

    // ---- epilogue: tanh(acc + w1q) * v, reduce N, scatter via rowmap ----
    const int q = lane >> 2;
    float* red = (float*)smem;
    __syncthreads();                                  // done with MMA smem

#pragma unroll
    for (int mt = 0; mt < 4; mt++) {
        int r_lo = row0 + mw * 64 + mt * 16 + q;
        int r_hi = r_lo + 8;
        int b_lo = g_rowmap[r_lo] >> 11;
        int b_hi = g_rowmap[r_hi] >> 11;
        if (b_lo > BQ - 1) b_lo = BQ - 1;
        if (b_hi > BQ - 1) b_hi = BQ - 1;
        float p0 = 0.f, p1 = 0.f;
#pragma unroll
        for (int n8 = 0; n8 < 4; n8++) {
            int cg = col0 + nwp * 32 + n8 * 8 + (lane & 3) * 2;
            float2 w1a = *(const float2*)(g_w1q + b_lo * DQ + cg);
            float2 w1b = *(const float2*)(g_w1q + b_hi * DQ + cg);
            float2 vv = *(const float2*)(v + cg);
            float* d = acc[mt][n8];
            p0 += fast_tanh(d[0] + w1a.x) * vv.x + fast_tanh(d[1] + w1a.y) * vv.y;
            p1 += fast_tanh(d[2] + w1b.x) * vv.x + fast_tanh(d[3] + w1b.y) * vv.y;
        }
        p0 += __shfl_xor_sync(0xffffffff, p0, 1);
        p0 += __shfl_xor_sync(0xffffffff, p0, 2);
        p1 += __shfl_xor_sync(0xffffffff, p1, 1);
        p1 += __shfl_xor_sync(0xffffffff, p1, 2);
        if ((lane & 3) == 0) {
            int r = mw * 64 + mt * 16 + q;
            red[nwp * 128 + r]     = p0;
            red[nwp * 128 + r + 8] = p1;
        }
    }
    __syncthreads();
    if (tid < 128) {
        float s = 0.f;
#pragma unroll
        for (int w = 0; w < 8; w++) s += red[w * 128 + tid];
        g_partial[blockIdx.x][g_rowmap[row0 + tid]] = s;
    }
}

// ---------------------------------------------------------------------------
// K6: masked softmax (mask int32). One block per batch row.
// ---------------------------------------------------------------------------
__global__ void __launch_bounds__(256) softmax_kernel(const int* __restrict__ mask,
                                                      float* __restrict__ out) {
    const int b = blockIdx.x, tid = threadIdx.x;
    __shared__ float red[256];

    float vals[8];
    float mx = -INFINITY;
#pragma unroll
    for (int t = 0; t < 8; t++) {
        int gi = b * SDIM + tid + t * 256;
        float sc = g_partial[0][gi] + g_partial[1][gi];
        sc = mask[gi] ? sc : -INFINITY;
        vals[t] = sc;
        mx = fmaxf(mx, sc);
    }
    red[tid] = mx;
    __syncthreads();
    for (int o = 128; o; o >>= 1) {
        if (tid < o) red[tid] = fmaxf(red[tid], red[tid + o]);
        __syncthreads();
    }
    mx = red[0];
    __syncthreads();

    float sum = 0.f;
#pragma unroll
    for (int t = 0; t < 8; t++) {
        vals[t] = expf(vals[t] - mx);
        sum += vals[t];
    }
    red[tid] = sum;
    __syncthreads();
    for (int o = 128; o; o >>= 1) {
        if (tid < o) red[tid] += red[tid + o];
        __syncthreads();
    }
    float inv = 1.f / red[0];
#pragma unroll
    for (int t = 0; t < 8; t++) out[b * SDIM + tid + t * 256] = vals[t] * inv;
}

// ---------------------------------------------------------------------------
// Launch
// ---------------------------------------------------------------------------
extern "C" void kernel_launch(void* const* d_in, const int* in_sizes, int n_in,
                              void* d_out, int out_size) {
    const float* query = (const float*)d_in[0];
    const float* keys  = (const float*)d_in[1];
    const int*   mask  = (const int*)d_in[2];
    const float* W1    = (const float*)d_in[3];
    const float* W2    = (const float*)d_in[4];
    const float* v     = (const float*)d_in[5];
    float*       out   = (float*)d_out;

    static bool attr_set = false;
    if (!attr_set) {
        cudaFuncSetAttribute(gemm_kernel, cudaFuncAttributeMaxDynamicSharedMemorySize,
                             SMEM_TOTAL);
        attr_set = true;
    }

    mask_count<<<256, 256>>>(mask);
    mask_scan<<<1, 256>>>();
    mask_scatter<<<256, 256>>>(mask);
    convert_w2<<<512, 256>>>(W2);
    w1q_kernel<<<dim3(4, BQ), 128>>>(query, W1);
    gemm_kernel<<<dim3(2, 512), 512, SMEM_TOTAL>>>(keys, v);
    softmax_kernel<<<BQ, 256>>>(mask, out);
}